// round 1
// baseline (speedup 1.0000x reference)
#include <cuda_runtime.h>
#include <cstdint>

#define N_NODES 100000
#define N_EDGES 1600000
#define D 128

// Scratch: aggregation buffer (51.2 MB) + index-width flag. Device globals (no allocation).
__device__ float g_agg[(size_t)N_NODES * D];
__device__ int g_idx64;

// ---------------------------------------------------------------------------
// Detect whether index arrays are int64 or int32.
// If the buffer really holds int64 indices, every 8-byte value is in [0, N).
// If it holds int32 indices, an 8-byte read combines two random indices; the
// high word is nonzero with prob ~0.99999 per entry -> 128 entries all "valid"
// is impossible in practice.
// ---------------------------------------------------------------------------
__global__ void detect_idx_kernel(const void* __restrict__ src_raw) {
    const long long* p = (const long long*)src_raw;
    int ok = 1;
    for (int i = 0; i < 128; i++) {
        long long v = p[i];
        if (v < 0 || v >= N_NODES) { ok = 0; break; }
    }
    g_idx64 = ok;
}

// ---------------------------------------------------------------------------
// Zero the aggregation buffer (float4 stores).
// ---------------------------------------------------------------------------
__global__ void zero_agg_kernel() {
    int i = blockIdx.x * blockDim.x + threadIdx.x;
    const int n4 = N_NODES * D / 4;
    if (i < n4) {
        ((float4*)g_agg)[i] = make_float4(0.f, 0.f, 0.f, 0.f);
    }
}

// ---------------------------------------------------------------------------
// Edge scatter: 32 threads per edge, each thread moves one float4.
// agg[dst[e]] += x[src[e]] via red.global.add.v4.f32 (L2-native vector atomic).
// ---------------------------------------------------------------------------
__global__ __launch_bounds__(256) void scatter_kernel(
    const float* __restrict__ x,
    const void* __restrict__ src_raw,
    const void* __restrict__ dst_raw)
{
    long long gid = (long long)blockIdx.x * blockDim.x + threadIdx.x;
    int e  = (int)(gid >> 5);
    int ln = (int)(gid & 31);
    if (e >= N_EDGES) return;

    int s, d;
    if (g_idx64) {
        s = (int)((const long long*)src_raw)[e];
        d = (int)((const long long*)dst_raw)[e];
    } else {
        s = ((const int*)src_raw)[e];
        d = ((const int*)dst_raw)[e];
    }

    float4 v = *(const float4*)(x + (size_t)s * D + ln * 4);
    float* out = g_agg + (size_t)d * D + ln * 4;
    asm volatile("red.global.add.v4.f32 [%0], {%1,%2,%3,%4};"
                 :: "l"(out), "f"(v.x), "f"(v.y), "f"(v.z), "f"(v.w)
                 : "memory");
}

// ---------------------------------------------------------------------------
// Dense GEMM + bias: out[n][o] = sum_i agg[n][i] * W[o][i] + b[o]
// One warp per row. W is staged transposed in smem (Wt[i][o]) so each lane
// reads a conflict-free float4 of 4 output columns; the agg row is held in
// registers and broadcast via shfl.
// ---------------------------------------------------------------------------
#define GEMM_BLOCKS 444
#define GEMM_THREADS 256

__global__ __launch_bounds__(GEMM_THREADS) void gemm_kernel(
    const float* __restrict__ W,
    const float* __restrict__ b,
    float* __restrict__ out)
{
    extern __shared__ float smem[];
    float* Wt = smem;            // [D][D], Wt[i*D + o] = W[o*D + i]  (64 KB)
    float* bs = smem + D * D;    // [D]

    int tid = threadIdx.x;
    for (int idx = tid; idx < D * D; idx += GEMM_THREADS) {
        int o = idx / D, i = idx % D;
        Wt[i * D + o] = W[idx];
    }
    if (tid < D) bs[tid] = b[tid];
    __syncthreads();

    int warp = tid >> 5;
    int ln   = tid & 31;
    const int warps_total = GEMM_BLOCKS * (GEMM_THREADS / 32);

    for (int row = blockIdx.x * (GEMM_THREADS / 32) + warp;
         row < N_NODES;
         row += warps_total)
    {
        // Row of agg held across the warp: lane ln owns elements [ln*4, ln*4+4)
        float4 r = *(const float4*)(g_agg + (size_t)row * D + ln * 4);
        // Each lane computes output columns [ln*4, ln*4+4)
        float4 acc = *(const float4*)(bs + ln * 4);

        #pragma unroll
        for (int j = 0; j < 4; j++) {
            float rj = (j == 0) ? r.x : (j == 1) ? r.y : (j == 2) ? r.z : r.w;
            #pragma unroll
            for (int sl = 0; sl < 32; sl++) {
                float a = __shfl_sync(0xffffffffu, rj, sl);
                int i = sl * 4 + j;
                float4 w = *(const float4*)(Wt + i * D + ln * 4);
                acc.x += a * w.x;
                acc.y += a * w.y;
                acc.z += a * w.z;
                acc.w += a * w.w;
            }
        }

        *(float4*)(out + (size_t)row * D + ln * 4) = acc;
    }
}

// ---------------------------------------------------------------------------
// Launch
// ---------------------------------------------------------------------------
extern "C" void kernel_launch(void* const* d_in, const int* in_sizes, int n_in,
                              void* d_out, int out_size) {
    const float* x   = (const float*)d_in[0];
    const void*  src = d_in[1];
    const void*  dst = d_in[2];
    const float* W   = (const float*)d_in[3];
    const float* b   = (const float*)d_in[4];
    float* out = (float*)d_out;

    static int smem_set = 0;
    if (!smem_set) {
        cudaFuncSetAttribute(gemm_kernel,
                             cudaFuncAttributeMaxDynamicSharedMemorySize,
                             (D * D + D) * (int)sizeof(float));
        smem_set = 1;
    }

    detect_idx_kernel<<<1, 1>>>(src);

    {
        int n4 = N_NODES * D / 4;
        zero_agg_kernel<<<(n4 + 255) / 256, 256>>>();
    }

    {
        long long total = (long long)N_EDGES * 32;
        int blocks = (int)((total + 255) / 256);
        scatter_kernel<<<blocks, 256>>>(x, src, dst);
    }

    gemm_kernel<<<GEMM_BLOCKS, GEMM_THREADS,
                  (D * D + D) * (int)sizeof(float)>>>(W, b, out);
}